// round 5
// baseline (speedup 1.0000x reference)
#include <cuda_runtime.h>

#define NEGV (-1000000000.0f)
#define NEGH (-5.0e8f)

static constexpr int Bb   = 8;
static constexpr int Nn   = 6000;
static constexpr int Cc   = 21;
static constexpr int MAXT = 200;
static constexpr int TS   = 1024;     // NMS block size
static constexpr int NW   = TS / 32;  // 32 warps
static constexpr int MSORT= 4096;     // sort capacity (cnt ~2857 for these inputs)

// ------------------------- scratch (device globals; no allocs) -------------
__device__ float4 g_boxes [Bb * Cc * Nn];
__device__ float  g_scores[Bb * Cc * Nn];
__device__ int    g_valid [Bb * Nn];
__device__ float  g_selval[Bb * Cc * MAXT];
__device__ float4 g_selbox[Bb * Cc * MAXT];

// ------------------------- kernel 0: per-(b,n) argmax flag -----------------
__global__ void k_valid(const float* __restrict__ probs)
{
    int i = blockIdx.x * blockDim.x + threadIdx.x;
    if (i >= Bb * Nn) return;
    const float* p = probs + (size_t)i * Cc;
    float best = p[0];
    int   lbl  = 0;
#pragma unroll
    for (int c = 1; c < Cc; c++) {
        float v = p[c];
        if (v > best) { best = v; lbl = c; }
    }
    g_valid[i] = (lbl != 0);
}

// ------------------------- kernel 1: decode, thread per (b,n,c) ------------
// Rounding identical to the passing R3/R4 version (bit-exact vs reference).
__global__ void k_decode2(const float* __restrict__ roi,
                          const float* __restrict__ deltas,
                          const float* __restrict__ probs)
{
    int t = blockIdx.x * blockDim.x + threadIdx.x;   // (b*N+n)*Cc + c
    if (t >= Bb * Nn * Cc) return;
    int i = t / Cc;
    int c = t - i * Cc;
    int b = i / Nn;
    int n = i - b * Nn;

    float sc = g_valid[i] ? probs[t] : 0.f;
    sc = (sc > 0.5f) ? sc : NEGV;

    size_t base = (size_t)(b * Cc + c) * Nn + n;     // [B][C][N]
    g_scores[base] = sc;
    if (sc > NEGH) {
        float4 r  = *(const float4*)(roi + (size_t)i * 4);
        float ah = __fsub_rn(r.z, r.x);
        float aw = __fsub_rn(r.w, r.y);
        float cy = __fmaf_rn(0.5f, ah, r.x);
        float cx = __fmaf_rn(0.5f, aw, r.y);

        float4 d = *(const float4*)(deltas + (size_t)t * 4);
        float dy = __fmul_rn(d.x, 0.1f);
        float dx = __fmul_rn(d.y, 0.1f);
        float dh = __fmul_rn(d.z, 0.2f);
        float dw = __fmul_rn(d.w, 0.2f);
        float bh  = __fmul_rn(expf(dh), ah);
        float bw  = __fmul_rn(expf(dw), aw);
        float bcy = __fmaf_rn(dy, ah, cy);
        float bcx = __fmaf_rn(dx, aw, cx);
        float y1 = __fmaf_rn(-0.5f, bh, bcy);
        float x1 = __fmaf_rn(-0.5f, bw, bcx);
        float y2 = __fadd_rn(y1, bh);
        float x2 = __fadd_rn(x1, bw);
        y1 = fminf(fmaxf(y1, 0.f), 1.f);
        x1 = fminf(fmaxf(x1, 0.f), 1.f);
        y2 = fminf(fmaxf(y2, 0.f), 1.f);
        x2 = fminf(fmaxf(x2, 0.f), 1.f);
        g_boxes[base] = make_float4(y1, x1, y2, x2);
    }
}

// ------------------------- IoU helper (exact reference op order) -----------
__device__ __forceinline__ bool iou_gt(const float4 sb, const float sa,
                                       const float4 cb, const float ca)
{
    float iy1 = fmaxf(sb.x, cb.x);
    float ix1 = fmaxf(sb.y, cb.y);
    float iy2 = fminf(sb.z, cb.z);
    float ix2 = fminf(sb.w, cb.w);
    float inter = __fmul_rn(fmaxf(__fsub_rn(iy2, iy1), 0.f),
                            fmaxf(__fsub_rn(ix2, ix1), 0.f));
    float denom = __fadd_rn(__fsub_rn(__fadd_rn(sa, ca), inter), 1e-8f);
    return __fdiv_rn(inter, denom) > 0.5f;
}

// ------------------------- kernel 2: sorted greedy NMS ---------------------
__global__ void __launch_bounds__(TS) k_nms()
{
    const int c  = blockIdx.x;
    const int b  = blockIdx.y;
    const int bc = b * Cc + c;
    const float*  sc_g = g_scores + (size_t)bc * Nn;
    const float4* bx_g = g_boxes  + (size_t)bc * Nn;

    __shared__ unsigned long long s_key[MSORT];  // (score_bits<<32)|(Nn-n): desc
    __shared__ int      s_cnt;
    __shared__ float4   s_selB[MAXT];
    __shared__ float    s_selA[MAXT];
    __shared__ float4   s_wbox[2][NW];
    __shared__ float    s_wa  [2][NW];
    __shared__ float    s_ws  [2][NW];
    __shared__ unsigned s_wm  [2][NW];

    const int tid  = threadIdx.x;
    const int lane = tid & 31;
    const int wid  = tid >> 5;

    for (int i = tid; i < MSORT; i += TS) s_key[i] = 0ull;   // padding sorts last
    if (tid == 0) s_cnt = 0;
    __syncthreads();

    // compaction order irrelevant: (score, idx) embedded in key
    for (int n = tid; n < Nn; n += TS) {
        float sc = sc_g[n];
        if (sc > NEGH) {
            int pos = atomicAdd(&s_cnt, 1);
            if (pos < MSORT)
                s_key[pos] = ((unsigned long long)__float_as_uint(sc) << 32)
                           | (unsigned int)(Nn - n);
        }
    }
    __syncthreads();
    int cnt = s_cnt;
    if (cnt > MSORT) cnt = MSORT;

    // bitonic sort, descending (4 elems/thread)
    for (int k = 2; k <= MSORT; k <<= 1) {
        for (int j = k >> 1; j > 0; j >>= 1) {
#pragma unroll
            for (int i0 = 0; i0 < MSORT; i0 += TS) {
                int i = i0 + tid;
                int ixj = i ^ j;
                if (ixj > i) {
                    unsigned long long a = s_key[i], bb = s_key[ixj];
                    bool desc = ((i & k) == 0);
                    if (desc ? (a < bb) : (a > bb)) { s_key[i] = bb; s_key[ixj] = a; }
                }
            }
            __syncthreads();
        }
    }

    float*  outv = g_selval + (size_t)bc * MAXT;
    float4* outb = g_selbox + (size_t)bc * MAXT;

    // ---- batched greedy walk: one ballot round per SELECTION ----
    int nsel = 0;
    int par  = 0;
    for (int p0 = 0; p0 < cnt && nsel < MAXT; p0 += TS) {
        int p = p0 + tid;
        bool has = (p < cnt);
        float4 cb = make_float4(0.f, 0.f, 0.f, 0.f);
        float  ca = 0.f, csc = 0.f;
        if (has) {
            unsigned long long key = s_key[p];
            int n = Nn - (int)(unsigned int)(key & 0xFFFFFFFFull);
            cb  = bx_g[n];
            ca  = __fmul_rn(fmaxf(__fsub_rn(cb.z, cb.x), 0.f),
                            fmaxf(__fsub_rn(cb.w, cb.y), 0.f));
            csc = __uint_as_float((unsigned int)(key >> 32));
        }
        bool alive = has;
        // pre-check against selections from earlier batches
        if (alive) {
            for (int s = 0; s < nsel; s++) {
                if (iou_gt(s_selB[s], s_selA[s], cb, ca)) { alive = false; break; }
            }
        }
        // in-order resolution within batch
        while (nsel < MAXT) {
            unsigned wm = __ballot_sync(0xffffffffu, alive);
            if (wm && lane == (unsigned)(__ffs(wm) - 1)) {
                s_wbox[par][wid] = cb;
                s_wa  [par][wid] = ca;
                s_ws  [par][wid] = csc;
            }
            if (lane == 0) s_wm[par][wid] = wm;
            __syncthreads();
            unsigned havew = __ballot_sync(0xffffffffu, s_wm[par][lane] != 0u);
            if (!havew) break;                       // uniform
            int w = __ffs(havew) - 1;
            float4 sb = s_wbox[par][w];
            float  sa = s_wa  [par][w];
            int winner = (w << 5) + (__ffs(s_wm[par][w]) - 1);
            if (tid == winner) {
                outv[nsel]   = s_ws[par][w];
                outb[nsel]   = sb;
                s_selB[nsel] = sb;
                s_selA[nsel] = sa;
                alive = false;
            }
            nsel++;
            par ^= 1;                                // double buffer
            if (alive && iou_gt(sb, sa, cb, ca)) alive = false;
        }
        __syncthreads();   // make winners' s_selB/s_selA visible to next batch
    }

    for (int t = nsel + tid; t < MAXT; t += TS) outv[t] = NEGV;
}

// ------------------------- kernel 3: merge 21 sorted lists -> top-200 ------
__global__ void __launch_bounds__(512) k_topk(float* __restrict__ out)
{
    int b = blockIdx.x;
    __shared__ float s_val[Cc * MAXT];
    __shared__ int   s_Vc[Cc];

    const float* gv = g_selval + (size_t)b * Cc * MAXT;
    for (int j = threadIdx.x; j < Cc * MAXT; j += blockDim.x) s_val[j] = gv[j];
    __syncthreads();

    if (threadIdx.x < Cc) {
        const float* L = s_val + threadIdx.x * MAXT;
        int lo = 0, hi = MAXT;
        while (lo < hi) { int m = (lo + hi) >> 1; if (L[m] > NEGH) lo = m + 1; else hi = m; }
        s_Vc[threadIdx.x] = lo;
    }
    __syncthreads();

    int V = 0;
#pragma unroll
    for (int cc = 0; cc < Cc; cc++) V += s_Vc[cc];

    float* ob = out + (size_t)b * MAXT * 4;                         // bboxes
    float* ol = out + (size_t)Bb * MAXT * 4 + (size_t)b * MAXT;     // labels
    float* os = out + (size_t)Bb * MAXT * 5 + (size_t)b * MAXT;     // scores

    for (int r = V + (int)threadIdx.x; r < MAXT; r += blockDim.x) {
        os[r] = 0.f; ol[r] = 0.f;
        ((float4*)ob)[r] = make_float4(0.f, 0.f, 0.f, 0.f);
    }

    for (int j = threadIdx.x; j < Cc * MAXT; j += blockDim.x) {
        int c = j / MAXT, t = j - c * MAXT;
        if (t >= s_Vc[c]) continue;
        float v = s_val[j];
        int rank = t;
        for (int c2 = 0; c2 < Cc; c2++) {
            if (c2 == c) continue;
            const float* L = s_val + c2 * MAXT;
            int lo = 0, hi = s_Vc[c2];
            if (c2 < c) {
                while (lo < hi) { int m = (lo + hi) >> 1; if (L[m] >= v) lo = m + 1; else hi = m; }
            } else {
                while (lo < hi) { int m = (lo + hi) >> 1; if (L[m] >  v) lo = m + 1; else hi = m; }
            }
            rank += lo;
        }
        if (rank < MAXT) {
            os[rank] = v;
            ol[rank] = (float)c;
            ((float4*)ob)[rank] = g_selbox[(size_t)b * Cc * MAXT + j];
        }
    }
}

// ------------------------- launch ------------------------------------------
extern "C" void kernel_launch(void* const* d_in, const int* in_sizes, int n_in,
                              void* d_out, int out_size)
{
    const float* roi    = (const float*)d_in[0];
    const float* deltas = (const float*)d_in[1];
    const float* probs  = (const float*)d_in[2];
    float* out = (float*)d_out;

    k_valid  <<<(Bb * Nn + 255) / 256, 256>>>(probs);
    k_decode2<<<(Bb * Nn * Cc + 255) / 256, 256>>>(roi, deltas, probs);
    dim3 g2(Cc, Bb);
    k_nms<<<g2, TS>>>();
    k_topk<<<Bb, 512>>>(out);
}

// round 6
// speedup vs baseline: 1.8047x; 1.8047x over previous
#include <cuda_runtime.h>

#define NEGV (-1000000000.0f)
#define NEGH (-5.0e8f)

static constexpr int Bb   = 8;
static constexpr int Nn   = 6000;
static constexpr int Cc   = 21;
static constexpr int MAXT = 200;
static constexpr int TS   = 256;      // NMS block size (one wave on 148 SMs)
static constexpr int NW   = TS / 32;  // 8 warps
static constexpr int MSORT= 4096;     // sort capacity (cnt ~2857 for these inputs)

// ------------------------- scratch (device globals; no allocs) -------------
__device__ float4 g_boxes [Bb * Cc * Nn];
__device__ float  g_scores[Bb * Cc * Nn];
__device__ float  g_selval[Bb * Cc * MAXT];
__device__ float4 g_selbox[Bb * Cc * MAXT];

// ------------------------- kernel 1: decode + score (R4 proven) ------------
__global__ void k_decode(const float* __restrict__ roi,
                         const float* __restrict__ deltas,
                         const float* __restrict__ probs)
{
    int i = blockIdx.x * blockDim.x + threadIdx.x;   // (b*N + n)
    if (i >= Bb * Nn) return;
    int b = i / Nn;
    int n = i - b * Nn;

    const float* p = probs + (size_t)i * Cc;
    float pv[Cc];
#pragma unroll
    for (int c = 0; c < Cc; c++) pv[c] = p[c];
    float best = pv[0];
    int   lbl  = 0;
#pragma unroll
    for (int c = 1; c < Cc; c++) {
        if (pv[c] > best) { best = pv[c]; lbl = c; }
    }

    float4 r  = *(const float4*)(roi + (size_t)i * 4);
    float ah = __fsub_rn(r.z, r.x);
    float aw = __fsub_rn(r.w, r.y);
    float cy = __fmaf_rn(0.5f, ah, r.x);
    float cx = __fmaf_rn(0.5f, aw, r.y);

    const float4* d4 = (const float4*)(deltas + (size_t)i * Cc * 4);
#pragma unroll
    for (int c = 0; c < Cc; c++) {
        float4 d  = d4[c];
        float dy = __fmul_rn(d.x, 0.1f);
        float dx = __fmul_rn(d.y, 0.1f);
        float dh = __fmul_rn(d.z, 0.2f);
        float dw = __fmul_rn(d.w, 0.2f);
        float bh  = __fmul_rn(expf(dh), ah);
        float bw  = __fmul_rn(expf(dw), aw);
        float bcy = __fmaf_rn(dy, ah, cy);
        float bcx = __fmaf_rn(dx, aw, cx);
        float y1 = __fmaf_rn(-0.5f, bh, bcy);
        float x1 = __fmaf_rn(-0.5f, bw, bcx);
        float y2 = __fadd_rn(y1, bh);
        float x2 = __fadd_rn(x1, bw);
        y1 = fminf(fmaxf(y1, 0.f), 1.f);
        x1 = fminf(fmaxf(x1, 0.f), 1.f);
        y2 = fminf(fmaxf(y2, 0.f), 1.f);
        x2 = fminf(fmaxf(x2, 0.f), 1.f);

        float sc = (lbl != 0) ? pv[c] : 0.f;
        sc = (sc > 0.5f) ? sc : NEGV;

        size_t base = (size_t)(b * Cc + c) * Nn + n; // [B][C][N]
        g_scores[base] = sc;
        if (sc > NEGH)
            g_boxes[base] = make_float4(y1, x1, y2, x2);
    }
}

// ------------------------- IoU helper (exact reference op order) -----------
__device__ __forceinline__ bool iou_gt(const float4 sb, const float sa,
                                       const float4 cb, const float ca)
{
    float iy1 = fmaxf(sb.x, cb.x);
    float ix1 = fmaxf(sb.y, cb.y);
    float iy2 = fminf(sb.z, cb.z);
    float ix2 = fminf(sb.w, cb.w);
    float inter = __fmul_rn(fmaxf(__fsub_rn(iy2, iy1), 0.f),
                            fmaxf(__fsub_rn(ix2, ix1), 0.f));
    float denom = __fadd_rn(__fsub_rn(__fadd_rn(sa, ca), inter), 1e-8f);
    return __fdiv_rn(inter, denom) > 0.5f;
}

// ------------------------- kernel 2: sorted greedy NMS ---------------------
__global__ void __launch_bounds__(TS) k_nms()
{
    const int c  = blockIdx.x;
    const int b  = blockIdx.y;
    const int bc = b * Cc + c;
    const float*  sc_g = g_scores + (size_t)bc * Nn;
    const float4* bx_g = g_boxes  + (size_t)bc * Nn;

    __shared__ unsigned long long s_key[MSORT];  // (score_bits<<32)|(Nn-n): desc
    __shared__ int      s_cnt;
    __shared__ float4   s_selB[MAXT];
    __shared__ float    s_selA[MAXT];
    __shared__ float4   s_wbox[2][NW];
    __shared__ float    s_wa  [2][NW];
    __shared__ float    s_ws  [2][NW];
    __shared__ unsigned s_wm  [2][NW];

    const int tid  = threadIdx.x;
    const int lane = tid & 31;
    const int wid  = tid >> 5;

    for (int i = tid; i < MSORT; i += TS) s_key[i] = 0ull;   // padding sorts last
    if (tid == 0) s_cnt = 0;
    __syncthreads();

    // compaction order irrelevant: (score, idx) embedded in key
    for (int n = tid; n < Nn; n += TS) {
        float sc = sc_g[n];
        if (sc > NEGH) {
            int pos = atomicAdd(&s_cnt, 1);
            if (pos < MSORT)
                s_key[pos] = ((unsigned long long)__float_as_uint(sc) << 32)
                           | (unsigned int)(Nn - n);
        }
    }
    __syncthreads();
    int cnt = s_cnt;
    if (cnt > MSORT) cnt = MSORT;

    // bitonic sort, descending (16 elems/thread)
    for (int k = 2; k <= MSORT; k <<= 1) {
        for (int j = k >> 1; j > 0; j >>= 1) {
#pragma unroll 4
            for (int i = tid; i < MSORT; i += TS) {
                int ixj = i ^ j;
                if (ixj > i) {
                    unsigned long long a = s_key[i], bb = s_key[ixj];
                    bool desc = ((i & k) == 0);
                    if (desc ? (a < bb) : (a > bb)) { s_key[i] = bb; s_key[ixj] = a; }
                }
            }
            __syncthreads();
        }
    }

    float*  outv = g_selval + (size_t)bc * MAXT;
    float4* outb = g_selbox + (size_t)bc * MAXT;

    // ---- batched greedy walk: one light ballot round per SELECTION ----
    int nsel = 0;
    int par  = 0;
    for (int p0 = 0; p0 < cnt && nsel < MAXT; p0 += TS) {
        int p = p0 + tid;
        bool has = (p < cnt);
        float4 cb = make_float4(0.f, 0.f, 0.f, 0.f);
        float  ca = 0.f, csc = 0.f;
        if (has) {
            unsigned long long key = s_key[p];
            int n = Nn - (int)(unsigned int)(key & 0xFFFFFFFFull);
            cb  = bx_g[n];
            ca  = __fmul_rn(fmaxf(__fsub_rn(cb.z, cb.x), 0.f),
                            fmaxf(__fsub_rn(cb.w, cb.y), 0.f));
            csc = __uint_as_float((unsigned int)(key >> 32));
        }
        bool alive = has;
        // pre-check against selections from earlier batches
        if (alive) {
            for (int s = 0; s < nsel; s++) {
                if (iou_gt(s_selB[s], s_selA[s], cb, ca)) { alive = false; break; }
            }
        }
        // in-order resolution within batch
        while (nsel < MAXT) {
            unsigned wm = __ballot_sync(0xffffffffu, alive);
            if (wm && lane == (unsigned)(__ffs(wm) - 1)) {
                s_wbox[par][wid] = cb;
                s_wa  [par][wid] = ca;
                s_ws  [par][wid] = csc;
            }
            if (lane == 0) s_wm[par][wid] = wm;
            __syncthreads();
            bool mylive = (lane < NW) && (s_wm[par][lane] != 0u);
            unsigned havew = __ballot_sync(0xffffffffu, mylive);
            if (!havew) break;                       // uniform across block
            int w = __ffs(havew) - 1;
            float4 sb = s_wbox[par][w];
            float  sa = s_wa  [par][w];
            int winner = (w << 5) + (__ffs(s_wm[par][w]) - 1);
            if (tid == winner) {
                outv[nsel]   = s_ws[par][w];
                outb[nsel]   = sb;
                s_selB[nsel] = sb;
                s_selA[nsel] = sa;
                alive = false;
            }
            nsel++;                                  // uniform
            par ^= 1;                                // double buffer
            if (alive && iou_gt(sb, sa, cb, ca)) alive = false;
        }
        __syncthreads();   // winners' s_selB/s_selA visible to next batch pre-check
    }

    for (int t = nsel + tid; t < MAXT; t += TS) outv[t] = NEGV;
}

// ------------------------- kernel 3: merge 21 sorted lists -> top-200 ------
// grid (Cc, Bb): one block per class list; thread t ranks entry t.
// Stable top_k: rank = #(> v) + #(== v with smaller flat index).
__global__ void __launch_bounds__(256) k_topk(float* __restrict__ out)
{
    const int c = blockIdx.x;
    const int b = blockIdx.y;
    __shared__ float s_val[Cc * MAXT];
    __shared__ int   s_Vc[Cc];

    const float* gv = g_selval + (size_t)b * Cc * MAXT;
    for (int j = threadIdx.x; j < Cc * MAXT; j += blockDim.x) s_val[j] = gv[j];
    __syncthreads();

    if (threadIdx.x < Cc) {
        const float* L = s_val + threadIdx.x * MAXT;
        int lo = 0, hi = MAXT;
        while (lo < hi) { int m = (lo + hi) >> 1; if (L[m] > NEGH) lo = m + 1; else hi = m; }
        s_Vc[threadIdx.x] = lo;
    }
    __syncthreads();

    float* ob = out + (size_t)b * MAXT * 4;                         // bboxes [B,200,4]
    float* ol = out + (size_t)Bb * MAXT * 4 + (size_t)b * MAXT;     // labels [B,200]
    float* os = out + (size_t)Bb * MAXT * 5 + (size_t)b * MAXT;     // scores [B,200]

    if (c == 0) {   // zero-fill tail rows once per batch image
        int V = 0;
#pragma unroll
        for (int cc = 0; cc < Cc; cc++) V += s_Vc[cc];
        for (int r = V + (int)threadIdx.x; r < MAXT; r += blockDim.x) {
            os[r] = 0.f; ol[r] = 0.f;
            ((float4*)ob)[r] = make_float4(0.f, 0.f, 0.f, 0.f);
        }
    }

    int t = threadIdx.x;
    if (t < s_Vc[c]) {
        float v = s_val[c * MAXT + t];
        int rank = t;   // own class: earlier entries >= v with lower flat idx
#pragma unroll 1
        for (int c2 = 0; c2 < Cc; c2++) {
            if (c2 == c) continue;
            const float* L = s_val + c2 * MAXT;
            int lo = 0, hi = s_Vc[c2];
            if (c2 < c) {
                while (lo < hi) { int m = (lo + hi) >> 1; if (L[m] >= v) lo = m + 1; else hi = m; }
            } else {
                while (lo < hi) { int m = (lo + hi) >> 1; if (L[m] >  v) lo = m + 1; else hi = m; }
            }
            rank += lo;
        }
        if (rank < MAXT) {
            os[rank] = v;
            ol[rank] = (float)c;
            ((float4*)ob)[rank] = g_selbox[(size_t)b * Cc * MAXT + c * MAXT + t];
        }
    }
}

// ------------------------- launch ------------------------------------------
extern "C" void kernel_launch(void* const* d_in, const int* in_sizes, int n_in,
                              void* d_out, int out_size)
{
    const float* roi    = (const float*)d_in[0];
    const float* deltas = (const float*)d_in[1];
    const float* probs  = (const float*)d_in[2];
    float* out = (float*)d_out;

    k_decode<<<(Bb * Nn + 255) / 256, 256>>>(roi, deltas, probs);
    dim3 g2(Cc, Bb);
    k_nms<<<g2, TS>>>();
    k_topk<<<g2, 256>>>(out);
}

// round 7
// speedup vs baseline: 2.5447x; 1.4101x over previous
#include <cuda_runtime.h>

#define NEGV (-1000000000.0f)
#define NEGH (-5.0e8f)

static constexpr int Bb   = 8;
static constexpr int Nn   = 6000;
static constexpr int Cc   = 21;
static constexpr int MAXT = 200;
static constexpr int TS   = 256;      // NMS block size
static constexpr int NW   = TS / 32;  // 8 warps
static constexpr int CAP  = 1024;     // per-chunk sort capacity
static constexpr int NB   = 256;      // score histogram buckets

// ------------------------- scratch (device globals; no allocs) -------------
__device__ float4 g_boxes [Bb * Cc * Nn];
__device__ float  g_scores[Bb * Cc * Nn];
__device__ float  g_selval[Bb * Cc * MAXT];
__device__ float4 g_selbox[Bb * Cc * MAXT];

// ------------------------- kernel 1: decode + score (bit-exact) ------------
__global__ void k_decode(const float* __restrict__ roi,
                         const float* __restrict__ deltas,
                         const float* __restrict__ probs)
{
    int i = blockIdx.x * blockDim.x + threadIdx.x;   // (b*N + n)
    if (i >= Bb * Nn) return;
    int b = i / Nn;
    int n = i - b * Nn;

    const float* p = probs + (size_t)i * Cc;
    float pv[Cc];
#pragma unroll
    for (int c = 0; c < Cc; c++) pv[c] = p[c];
    float best = pv[0];
    int   lbl  = 0;
#pragma unroll
    for (int c = 1; c < Cc; c++) {
        if (pv[c] > best) { best = pv[c]; lbl = c; }
    }

    float4 r  = *(const float4*)(roi + (size_t)i * 4);
    float ah = __fsub_rn(r.z, r.x);
    float aw = __fsub_rn(r.w, r.y);
    float cy = __fmaf_rn(0.5f, ah, r.x);
    float cx = __fmaf_rn(0.5f, aw, r.y);

    const float4* d4 = (const float4*)(deltas + (size_t)i * Cc * 4);
#pragma unroll
    for (int c = 0; c < Cc; c++) {
        float4 d  = d4[c];
        float dy = __fmul_rn(d.x, 0.1f);
        float dx = __fmul_rn(d.y, 0.1f);
        float dh = __fmul_rn(d.z, 0.2f);
        float dw = __fmul_rn(d.w, 0.2f);
        float bh  = __fmul_rn(expf(dh), ah);
        float bw  = __fmul_rn(expf(dw), aw);
        float bcy = __fmaf_rn(dy, ah, cy);
        float bcx = __fmaf_rn(dx, aw, cx);
        float y1 = __fmaf_rn(-0.5f, bh, bcy);
        float x1 = __fmaf_rn(-0.5f, bw, bcx);
        float y2 = __fadd_rn(y1, bh);
        float x2 = __fadd_rn(x1, bw);
        y1 = fminf(fmaxf(y1, 0.f), 1.f);
        x1 = fminf(fmaxf(x1, 0.f), 1.f);
        y2 = fminf(fmaxf(y2, 0.f), 1.f);
        x2 = fminf(fmaxf(x2, 0.f), 1.f);

        float sc = (lbl != 0) ? pv[c] : 0.f;
        sc = (sc > 0.5f) ? sc : NEGV;

        size_t base = (size_t)(b * Cc + c) * Nn + n; // [B][C][N]
        g_scores[base] = sc;
        if (sc > NEGH)
            g_boxes[base] = make_float4(y1, x1, y2, x2);
    }
}

// ------------------------- IoU helper (exact reference op order) -----------
__device__ __forceinline__ bool iou_gt(const float4 sb, const float sa,
                                       const float4 cb, const float ca)
{
    float iy1 = fmaxf(sb.x, cb.x);
    float ix1 = fmaxf(sb.y, cb.y);
    float iy2 = fminf(sb.z, cb.z);
    float ix2 = fminf(sb.w, cb.w);
    float inter = __fmul_rn(fmaxf(__fsub_rn(iy2, iy1), 0.f),
                            fmaxf(__fsub_rn(ix2, ix1), 0.f));
    float denom = __fadd_rn(__fsub_rn(__fadd_rn(sa, ca), inter), 1e-8f);
    return __fdiv_rn(inter, denom) > 0.5f;
}

// ------------------------- kernel 2: chunked sorted greedy NMS -------------
// Scores live in (0.5, 1.0): float exponent constant -> (bits>>15)&0xFF is a
// monotone 8-bit bucket of score. Process buckets top-down in chunks of <=CAP
// candidates; within a chunk, full bitonic sort of (score,idx) keys; greedy
// walk with persistent selection state. Identical order to a full sort.
__global__ void __launch_bounds__(TS) k_nms()
{
    const int c  = blockIdx.x;
    const int b  = blockIdx.y;
    const int bc = b * Cc + c;
    const float*  sc_g = g_scores + (size_t)bc * Nn;
    const float4* bx_g = g_boxes  + (size_t)bc * Nn;

    __shared__ unsigned long long s_key[CAP];    // (score_bits<<32)|(Nn-n): desc
    __shared__ int      s_hist[NB];
    __shared__ int      s_cnt;
    __shared__ int      s_lo;
    __shared__ float4   s_selB[MAXT];
    __shared__ float    s_selA[MAXT];
    __shared__ float4   s_wbox[2][NW];
    __shared__ float    s_wa  [2][NW];
    __shared__ float    s_ws  [2][NW];
    __shared__ unsigned s_wm  [2][NW];

    const int tid  = threadIdx.x;
    const int lane = tid & 31;
    const int wid  = tid >> 5;

    for (int i = tid; i < NB; i += TS) s_hist[i] = 0;
    __syncthreads();

    // histogram of candidate score buckets
    for (int n = tid; n < Nn; n += TS) {
        float sc = sc_g[n];
        if (sc > NEGH)
            atomicAdd(&s_hist[(__float_as_uint(sc) >> 15) & 0xFF], 1);
    }
    __syncthreads();

    float*  outv = g_selval + (size_t)bc * MAXT;
    float4* outb = g_selbox + (size_t)bc * MAXT;

    int nsel = 0;
    int par  = 0;
    int hiB  = NB;                                // exclusive upper bucket

    while (nsel < MAXT && hiB > 0) {
        // thread 0 picks the chunk's bucket range [lo, hiB)
        if (tid == 0) {
            int cum = 0, lo = hiB;
            while (lo > 0) {
                int cnt = s_hist[lo - 1];
                if (cum + cnt > CAP && cum > 0) break;
                cum += cnt;
                lo--;
                if (cum > CAP) break;            // single huge bucket: clamp below
            }
            s_lo  = lo;
            s_cnt = 0;
        }
        __syncthreads();
        const int loB = s_lo;
        __syncthreads();

        // collect chunk candidates
        for (int n = tid; n < Nn; n += TS) {
            float sc = sc_g[n];
            if (sc > NEGH) {
                unsigned bits = __float_as_uint(sc);
                int bk = (bits >> 15) & 0xFF;
                if (bk >= loB && bk < hiB) {
                    int pos = atomicAdd(&s_cnt, 1);
                    if (pos < CAP)
                        s_key[pos] = ((unsigned long long)bits << 32)
                                   | (unsigned int)(Nn - n);
                }
            }
        }
        __syncthreads();
        int cntc = s_cnt;
        if (cntc > CAP) cntc = CAP;

        if (cntc > 0) {
            // pad to pow2 and bitonic sort (descending; 0 pads sort last)
            int M = 2;
            while (M < cntc) M <<= 1;
            for (int i = cntc + tid; i < M; i += TS) s_key[i] = 0ull;
            __syncthreads();
            for (int k = 2; k <= M; k <<= 1) {
                for (int j = k >> 1; j > 0; j >>= 1) {
                    for (int i = tid; i < M; i += TS) {
                        int ixj = i ^ j;
                        if (ixj > i) {
                            unsigned long long a = s_key[i], bb = s_key[ixj];
                            bool desc = ((i & k) == 0);
                            if (desc ? (a < bb) : (a > bb)) { s_key[i] = bb; s_key[ixj] = a; }
                        }
                    }
                    __syncthreads();
                }
            }

            // batched greedy walk over this chunk
            for (int p0 = 0; p0 < cntc && nsel < MAXT; p0 += TS) {
                int p = p0 + tid;
                bool has = (p < cntc);
                float4 cb = make_float4(0.f, 0.f, 0.f, 0.f);
                float  ca = 0.f, csc = 0.f;
                if (has) {
                    unsigned long long key = s_key[p];
                    int n = Nn - (int)(unsigned int)(key & 0xFFFFFFFFull);
                    cb  = bx_g[n];
                    ca  = __fmul_rn(fmaxf(__fsub_rn(cb.z, cb.x), 0.f),
                                    fmaxf(__fsub_rn(cb.w, cb.y), 0.f));
                    csc = __uint_as_float((unsigned int)(key >> 32));
                }
                bool alive = has;
                if (alive) {                           // vs earlier selections
                    for (int s = 0; s < nsel; s++) {
                        if (iou_gt(s_selB[s], s_selA[s], cb, ca)) { alive = false; break; }
                    }
                }
                while (nsel < MAXT) {                  // in-order within batch
                    unsigned wm = __ballot_sync(0xffffffffu, alive);
                    if (wm && lane == (unsigned)(__ffs(wm) - 1)) {
                        s_wbox[par][wid] = cb;
                        s_wa  [par][wid] = ca;
                        s_ws  [par][wid] = csc;
                    }
                    if (lane == 0) s_wm[par][wid] = wm;
                    __syncthreads();
                    bool mylive = (lane < NW) && (s_wm[par][lane] != 0u);
                    unsigned havew = __ballot_sync(0xffffffffu, mylive);
                    if (!havew) break;                 // uniform
                    int w = __ffs(havew) - 1;
                    float4 sb = s_wbox[par][w];
                    float  sa = s_wa  [par][w];
                    int winner = (w << 5) + (__ffs(s_wm[par][w]) - 1);
                    if (tid == winner) {
                        outv[nsel]   = s_ws[par][w];
                        outb[nsel]   = sb;
                        s_selB[nsel] = sb;
                        s_selA[nsel] = sa;
                        alive = false;
                    }
                    nsel++;                            // uniform
                    par ^= 1;
                    if (alive && iou_gt(sb, sa, cb, ca)) alive = false;
                }
                __syncthreads();                       // selections visible
            }
        }
        hiB = loB;
        __syncthreads();                               // s_cnt reuse safe
    }

    for (int t = nsel + tid; t < MAXT; t += TS) outv[t] = NEGV;
}

// ------------------------- kernel 3: merge 21 sorted lists -> top-200 ------
__global__ void __launch_bounds__(256) k_topk(float* __restrict__ out)
{
    const int c = blockIdx.x;
    const int b = blockIdx.y;
    __shared__ float s_val[Cc * MAXT];
    __shared__ int   s_Vc[Cc];

    const float* gv = g_selval + (size_t)b * Cc * MAXT;
    for (int j = threadIdx.x; j < Cc * MAXT; j += blockDim.x) s_val[j] = gv[j];
    __syncthreads();

    if (threadIdx.x < Cc) {
        const float* L = s_val + threadIdx.x * MAXT;
        int lo = 0, hi = MAXT;
        while (lo < hi) { int m = (lo + hi) >> 1; if (L[m] > NEGH) lo = m + 1; else hi = m; }
        s_Vc[threadIdx.x] = lo;
    }
    __syncthreads();

    float* ob = out + (size_t)b * MAXT * 4;                         // bboxes [B,200,4]
    float* ol = out + (size_t)Bb * MAXT * 4 + (size_t)b * MAXT;     // labels [B,200]
    float* os = out + (size_t)Bb * MAXT * 5 + (size_t)b * MAXT;     // scores [B,200]

    if (c == 0) {   // zero-fill tail rows once per image
        int V = 0;
#pragma unroll
        for (int cc = 0; cc < Cc; cc++) V += s_Vc[cc];
        for (int r = V + (int)threadIdx.x; r < MAXT; r += blockDim.x) {
            os[r] = 0.f; ol[r] = 0.f;
            ((float4*)ob)[r] = make_float4(0.f, 0.f, 0.f, 0.f);
        }
    }

    int t = threadIdx.x;
    if (t < s_Vc[c]) {
        float v = s_val[c * MAXT + t];
        int rank = t;
#pragma unroll 1
        for (int c2 = 0; c2 < Cc; c2++) {
            if (c2 == c) continue;
            const float* L = s_val + c2 * MAXT;
            int lo = 0, hi = s_Vc[c2];
            if (c2 < c) {
                while (lo < hi) { int m = (lo + hi) >> 1; if (L[m] >= v) lo = m + 1; else hi = m; }
            } else {
                while (lo < hi) { int m = (lo + hi) >> 1; if (L[m] >  v) lo = m + 1; else hi = m; }
            }
            rank += lo;
        }
        if (rank < MAXT) {
            os[rank] = v;
            ol[rank] = (float)c;
            ((float4*)ob)[rank] = g_selbox[(size_t)b * Cc * MAXT + c * MAXT + t];
        }
    }
}

// ------------------------- launch ------------------------------------------
extern "C" void kernel_launch(void* const* d_in, const int* in_sizes, int n_in,
                              void* d_out, int out_size)
{
    const float* roi    = (const float*)d_in[0];
    const float* deltas = (const float*)d_in[1];
    const float* probs  = (const float*)d_in[2];
    float* out = (float*)d_out;

    k_decode<<<(Bb * Nn + 127) / 128, 128>>>(roi, deltas, probs);
    dim3 g2(Cc, Bb);
    k_nms<<<g2, TS>>>();
    k_topk<<<g2, 256>>>(out);
}